// round 1
// baseline (speedup 1.0000x reference)
#include <cuda_runtime.h>

#define NTHREADS 256
#define SAMPLES  32
#define HDIM     50
#define HP       56            // padded units: 7 per warp * 8 warps
#define G4       (4*HP)        // 224 interleaved gate columns per k-row
#define TSTEPS   256
#define NU       7
#define HSTRIDE  58            // even (float2-aligned), 29 odd -> conflict-free LDS64

typedef unsigned long long ull;

__device__ __forceinline__ ull pack2(float lo, float hi) {
    ull r; asm("mov.b64 %0, {%1,%2};" : "=l"(r) : "f"(lo), "f"(hi)); return r;
}
__device__ __forceinline__ void unpack2(ull v, float& lo, float& hi) {
    asm("mov.b64 {%0,%1}, %2;" : "=f"(lo), "=f"(hi) : "l"(v));
}
__device__ __forceinline__ ull fma2(ull a, ull b, ull c) {
    ull d; asm("fma.rn.f32x2 %0, %1, %2, %3;" : "=l"(d) : "l"(a), "l"(b), "l"(c)); return d;
}
__device__ __forceinline__ float sigmoidf_(float x) {
    return __fdividef(1.f, 1.f + __expf(-x));
}
__device__ __forceinline__ float tanhf_(float x) {
    return fmaf(2.f, sigmoidf_(2.f * x), -1.f);
}

// Dynamic shared layout (floats):
//  Ws  [50*224]   = 11200   : Ws[k*224 + 4*j + g] = W_hh[g*50+j][k], zero for j>=50
//  wx  [224]                : W_ih interleaved (gate-major -> 4j+g)
//  bbv [224]                : b_ih + b_hh interleaved
//  hb  [2*32*58]  = 3712    : double-buffered hidden state
//  xs  [32*33]    = 1056    : staged x tile (32 samples x 32 timesteps)
#define OFF_WS  0
#define OFF_WX  11200
#define OFF_BB  11424
#define OFF_HB  11648
#define OFF_XS  (11648 + 2*32*HSTRIDE)
#define SMEM_FLOATS (OFF_XS + 32*33)

__global__ void __launch_bounds__(NTHREADS, 1) lstm_q_kernel(
    const float* __restrict__ x,    const float* __restrict__ W_ih,
    const float* __restrict__ W_hh, const float* __restrict__ b_ih,
    const float* __restrict__ b_hh, const float* __restrict__ Wp,
    const float* __restrict__ bp,   const float* __restrict__ qw,
    const float* __restrict__ Wo,   const float* __restrict__ bo,
    float* __restrict__ out)
{
    extern __shared__ float sm[];
    float* Ws  = sm + OFF_WS;
    float* wx  = sm + OFF_WX;
    float* bbv = sm + OFF_BB;
    float* hb  = sm + OFF_HB;
    float* xs  = sm + OFF_XS;

    const int tid   = threadIdx.x;
    const int lane  = tid & 31;
    const int warp  = tid >> 5;
    const int bbase = blockIdx.x * SAMPLES;
    const int s     = lane;

    // ---- stage weights into shared (interleaved gate layout, zero-padded j>=50) ----
    for (int idx = tid; idx < 50 * G4; idx += NTHREADS) {
        int k = idx / G4, col = idx - k * G4;
        int j = col >> 2, g = col & 3;
        Ws[idx] = (j < HDIM) ? W_hh[(g * HDIM + j) * HDIM + k] : 0.f;
    }
    for (int idx = tid; idx < G4; idx += NTHREADS) {
        int j = idx >> 2, g = idx & 3;
        if (j < HDIM) {
            wx[idx]  = W_ih[g * HDIM + j];
            bbv[idx] = b_ih[g * HDIM + j] + b_hh[g * HDIM + j];
        } else { wx[idx] = 0.f; bbv[idx] = 0.f; }
    }
    for (int idx = tid; idx < 32 * HSTRIDE; idx += NTHREADS) hb[idx] = 0.f;

    float c_st[NU];
    #pragma unroll
    for (int u = 0; u < NU; u++) c_st[u] = 0.f;

    int buf = 0;

    for (int t = 0; t < TSTEPS; t++) {
        if ((t & 31) == 0) {
            __syncthreads();           // prior tile reads done
            for (int idx = tid; idx < 32 * 32; idx += NTHREADS) {
                int ss = idx >> 5, tt = idx & 31;
                xs[ss * 33 + tt] = x[(bbase + ss) * TSTEPS + t + tt];
            }
        }
        __syncthreads();               // h writes of prev step + xs refill visible

        float xv = xs[s * 33 + (t & 31)];
        ull  xv2 = pack2(xv, xv);
        const float* hrow = hb + buf * (32 * HSTRIDE) + s * HSTRIDE;

        ull acc_if[NU], acc_go[NU];
        #pragma unroll
        for (int u = 0; u < NU; u++) {
            int col = 4 * (warp + 8 * u);
            ulonglong2 wv = *(const ulonglong2*)(wx  + col);
            ulonglong2 bv = *(const ulonglong2*)(bbv + col);
            acc_if[u] = fma2(xv2, wv.x, bv.x);
            acc_go[u] = fma2(xv2, wv.y, bv.y);
        }

        #pragma unroll 5
        for (int k0 = 0; k0 < HDIM; k0 += 2) {
            float2 hp = *(const float2*)(hrow + k0);
            ull h0 = pack2(hp.x, hp.x);
            ull h1 = pack2(hp.y, hp.y);
            const float* wr0 = Ws + k0 * G4 + 4 * warp;
            const float* wr1 = wr0 + G4;
            #pragma unroll
            for (int u = 0; u < NU; u++) {
                ulonglong2 w0 = *(const ulonglong2*)(wr0 + 32 * u);
                acc_if[u] = fma2(h0, w0.x, acc_if[u]);
                acc_go[u] = fma2(h0, w0.y, acc_go[u]);
                ulonglong2 w1 = *(const ulonglong2*)(wr1 + 32 * u);
                acc_if[u] = fma2(h1, w1.x, acc_if[u]);
                acc_go[u] = fma2(h1, w1.y, acc_go[u]);
            }
        }

        float* hnew = hb + (buf ^ 1) * (32 * HSTRIDE) + s * HSTRIDE;
        #pragma unroll
        for (int u = 0; u < NU; u++) {
            float zi, zf, zg, zo;
            unpack2(acc_if[u], zi, zf);
            unpack2(acc_go[u], zg, zo);
            float ig = sigmoidf_(zi);
            float fg = sigmoidf_(zf);
            float gg = tanhf_(zg);
            float og = sigmoidf_(zo);
            float c  = fmaf(fg, c_st[u], ig * gg);
            c_st[u]  = c;
            hnew[warp + 8 * u] = og * tanhf_(c);
        }
        buf ^= 1;
    }

    __syncthreads();   // all final-h writes visible

    // ---------------- quantum head: 1 thread per sample ----------------
    if (tid < SAMPLES) {
        const float* hfin = hb + buf * (32 * HSTRIDE) + tid * HSTRIDE;

        float ang[4];
        #pragma unroll
        for (int w = 0; w < 4; w++) {
            float a = bp[w];
            for (int k = 0; k < HDIM; k++) a = fmaf(Wp[w * HDIM + k], hfin[k], a);
            ang[w] = tanhf_(a) * 1.5707963267948966f;
        }

        float re[16], im[16];
        #pragma unroll
        for (int i = 0; i < 16; i++) { re[i] = 0.f; im[i] = 0.f; }
        re[0] = 1.f;

        // RX embedding on each wire (wire w <-> bit 3-w)
        #pragma unroll
        for (int w = 0; w < 4; w++) {
            float sw, cw;
            sincosf(0.5f * ang[w], &sw, &cw);
            const int m = 8 >> w;
            #pragma unroll
            for (int i0 = 0; i0 < 16; i0++) {
                if (!(i0 & m)) {
                    int i1 = i0 | m;
                    float r0 = re[i0], q0 = im[i0], r1 = re[i1], q1 = im[i1];
                    re[i0] = cw * r0 + sw * q1;  im[i0] = cw * q0 - sw * r1;
                    re[i1] = cw * r1 + sw * q0;  im[i1] = cw * q1 - sw * r0;
                }
            }
        }

        // StronglyEntanglingLayers
        #pragma unroll
        for (int l = 0; l < 2; l++) {
            #pragma unroll
            for (int w = 0; w < 4; w++) {
                const float* q = qw + (l * 4 + w) * 3;
                float phi = q[0], th = q[1], om = q[2];
                float st_, ct_; sincosf(0.5f * th, &st_, &ct_);
                float sa, ca;   sincosf(0.5f * (phi + om), &sa, &ca);
                float sb, cb;   sincosf(0.5f * (phi - om), &sb, &cb);
                float u00r =  ct_ * ca, u00i = -ct_ * sa;   // e^{-i(phi+om)/2} ct
                float u01r = -st_ * cb, u01i = -st_ * sb;   // -e^{+i(phi-om)/2} st
                float u10r =  st_ * cb, u10i = -st_ * sb;   // e^{-i(phi-om)/2} st
                float u11r =  ct_ * ca, u11i =  ct_ * sa;   // e^{+i(phi+om)/2} ct
                const int m = 8 >> w;
                #pragma unroll
                for (int i0 = 0; i0 < 16; i0++) {
                    if (!(i0 & m)) {
                        int i1 = i0 | m;
                        float r0 = re[i0], q0 = im[i0], r1 = re[i1], q1 = im[i1];
                        re[i0] = u00r*r0 - u00i*q0 + u01r*r1 - u01i*q1;
                        im[i0] = u00r*q0 + u00i*r0 + u01r*q1 + u01i*r1;
                        re[i1] = u10r*r0 - u10i*q0 + u11r*r1 - u11i*q1;
                        im[i1] = u10r*q0 + u10i*r0 + u11r*q1 + u11i*r1;
                    }
                }
            }
            const int r = (l % 3) + 1;
            #pragma unroll
            for (int w = 0; w < 4; w++) {
                const int cm = 8 >> w;
                const int tm = 8 >> ((w + r) & 3);
                #pragma unroll
                for (int i0 = 0; i0 < 16; i0++) {
                    if ((i0 & cm) && !(i0 & tm)) {
                        int i1 = i0 | tm;
                        float tr = re[i0]; re[i0] = re[i1]; re[i1] = tr;
                        float ti = im[i0]; im[i0] = im[i1]; im[i1] = ti;
                    }
                }
            }
        }

        float o = bo[0];
        #pragma unroll
        for (int w = 0; w < 4; w++) {
            const int m = 8 >> w;
            float ev = 0.f;
            #pragma unroll
            for (int i = 0; i < 16; i++) {
                float p = re[i] * re[i] + im[i] * im[i];
                ev += (i & m) ? -p : p;
            }
            o = fmaf(Wo[w], ev, o);
        }
        out[bbase + tid] = o;
    }
}

extern "C" void kernel_launch(void* const* d_in, const int* in_sizes, int n_in,
                              void* d_out, int out_size) {
    const float* x    = (const float*)d_in[0];
    const float* W_ih = (const float*)d_in[1];
    const float* W_hh = (const float*)d_in[2];
    const float* b_ih = (const float*)d_in[3];
    const float* b_hh = (const float*)d_in[4];
    const float* Wp   = (const float*)d_in[5];
    const float* bp   = (const float*)d_in[6];
    const float* qw   = (const float*)d_in[7];
    const float* Wo   = (const float*)d_in[8];
    const float* bo   = (const float*)d_in[9];
    float* out = (float*)d_out;

    const size_t smem = SMEM_FLOATS * sizeof(float);
    cudaFuncSetAttribute(lstm_q_kernel, cudaFuncAttributeMaxDynamicSharedMemorySize, (int)smem);

    lstm_q_kernel<<<4096 / SAMPLES, NTHREADS, smem>>>(
        x, W_ih, W_hh, b_ih, b_hh, Wp, bp, qw, Wo, bo, out);
}